// round 14
// baseline (speedup 1.0000x reference)
#include <cuda_runtime.h>
#include <cuda_bf16.h>

typedef unsigned long long ull;

#define BB 8
#define NP 8192
#define NQ 1024
#define KNN 32
#define F1 64

#define FPS_T 256
#define FPS_PAIRS 16               // 32 points per thread

// scratch: neighbor indices (radius-resolved), B*N2*K
__device__ int g_nbr[BB * NQ * KNN];

// ---------------- packed f32x2 helpers ----------------
union F2 { ull u; float2 f; };

__device__ __forceinline__ ull add2(ull a, ull b)
{
    ull r; asm("add.rn.f32x2 %0, %1, %2;" : "=l"(r) : "l"(a), "l"(b)); return r;
}
__device__ __forceinline__ ull mul2(ull a, ull b)
{
    ull r; asm("mul.rn.f32x2 %0, %1, %2;" : "=l"(r) : "l"(a), "l"(b)); return r;
}
__device__ __forceinline__ void fma2(ull& d, ull a, ull b)
{
    asm("fma.rn.f32x2 %0, %1, %2, %0;" : "+l"(d) : "l"(a), "l"(b));
}
__device__ __forceinline__ ull bc2(float x)
{
    ull r; asm("mov.b64 %0, {%1, %1};" : "=l"(r) : "f"(x)); return r;
}
__device__ __forceinline__ float2 unpk(ull r)
{
    float2 v; asm("mov.b64 {%0, %1}, %2;" : "=f"(v.x), "=f"(v.y) : "l"(r)); return v;
}
__device__ __forceinline__ float lrelu(float x) { return fmaxf(x, 0.2f * x); }

// ---------------------------------------------------------------------------
// Kernel 1: FPS (unchanged from R12 — measured 494us). 1 block/batch, 256
// threads, 32 pts/thread (16 packed pairs), single barrier/step, REDUX argmax
// with exact lowest-global-index tie semantics.
// ---------------------------------------------------------------------------
__global__ void __launch_bounds__(FPS_T, 1) fps_kernel(const float* __restrict__ xyz,
                                                       float* __restrict__ out)
{
    extern __shared__ float s[];            // sx/sy/sz: 3*8192 floats = 96KB
    float* sx = s;
    float* sy = s + NP;
    float* sz = s + 2 * NP;
    __shared__ unsigned swh[2][32];
    __shared__ int      swl[2][32];

    const int b = blockIdx.x;
    const int t = threadIdx.x;
    const int lane = t & 31;
    const int wid = t >> 5;                 // 0..7
    const float* p = xyz + (size_t)b * NP * 3;

    ull px[FPS_PAIRS], py[FPS_PAIRS], pz[FPS_PAIRS];
    float md[2 * FPS_PAIRS];
    float pm[FPS_PAIRS];
#pragma unroll
    for (int i = 0; i < FPS_PAIRS; i++) {
        int i0 = t + (2 * i) * FPS_T;
        int i1 = t + (2 * i + 1) * FPS_T;
        F2 X, Y, Z;
        X.f.x = p[i0 * 3 + 0]; Y.f.x = p[i0 * 3 + 1]; Z.f.x = p[i0 * 3 + 2];
        X.f.y = p[i1 * 3 + 0]; Y.f.y = p[i1 * 3 + 1]; Z.f.y = p[i1 * 3 + 2];
        px[i] = X.u; py[i] = Y.u; pz[i] = Z.u;
        sx[i0] = X.f.x; sy[i0] = Y.f.x; sz[i0] = Z.f.x;
        sx[i1] = X.f.y; sy[i1] = Y.f.y; sz[i1] = Z.f.y;
        md[2 * i] = 3.402823466e38f;
        md[2 * i + 1] = 3.402823466e38f;
    }
    if (wid == 0 && lane >= 8) {            // pad unused stage-2 slots
        swh[0][lane] = 0u; swh[1][lane] = 0u;
        swl[0][lane] = 0x7fffffff; swl[1][lane] = 0x7fffffff;
    }
    if (t == 0) {
        float* o = out + (size_t)b * NQ * 3;
        o[0] = p[0]; o[1] = p[1]; o[2] = p[2];
    }
    __syncthreads();

    float wx = p[0], wy = p[1], wz = p[2];  // current center (every thread)
    unsigned par = 0;
    for (int si = 1; si < NQ; si++) {
        const ull ncx = bc2(-wx), ncy = bc2(-wy), ncz = bc2(-wz);
        float tv = -1.0f;
#pragma unroll
        for (int i = 0; i < FPS_PAIRS; i++) {
            ull dx = add2(px[i], ncx);
            ull dy = add2(py[i], ncy);
            ull dz = add2(pz[i], ncz);
            ull d = mul2(dx, dx);
            fma2(d, dy, dy);
            fma2(d, dz, dz);
            float2 D = unpk(d);
            float m0 = fminf(md[2 * i], D.x);
            float m1 = fminf(md[2 * i + 1], D.y);
            md[2 * i] = m0;
            md[2 * i + 1] = m1;
            float pv = fmaxf(m0, m1);
            pm[i] = pv;
            tv = fmaxf(tv, pv);
        }
        // warp argmax via redux (all md >= 0 -> uint order == float order)
        const unsigned hi = __reduce_max_sync(0xffffffffu, __float_as_uint(tv));
        int cand = 0x7fffffff;
#pragma unroll
        for (int i = FPS_PAIRS - 1; i >= 0; i--) {
            if (__float_as_uint(pm[i]) == hi) {
                int slot = (__float_as_uint(md[2 * i]) == hi) ? (2 * i) : (2 * i + 1);
                cand = t + (slot << 8);     // global idx = t + slot*256
            }
        }
        const unsigned lo = __reduce_min_sync(0xffffffffu, (unsigned)cand);
        if (lane == 0) { swh[par][wid] = hi; swl[par][wid] = (int)lo; }
        __syncthreads();                                   // single barrier
        const unsigned h2 = swh[par][lane];
        const unsigned hh = __reduce_max_sync(0xffffffffu, h2);
        const unsigned c2 = (h2 == hh) ? (unsigned)swl[par][lane] : 0x7fffffffu;
        const int id = (int)__reduce_min_sync(0xffffffffu, c2);
        wx = sx[id]; wy = sy[id]; wz = sz[id];             // broadcast LDS
        if (t == 0) {
            float* o2 = out + (size_t)b * NQ * 3 + si * 3;
            o2[0] = wx; o2[1] = wy; o2[2] = wz;
        }
        par ^= 1;
    }
}

// ---------------------------------------------------------------------------
// Kernel 2: warp-per-query 32-NN, radius pre-prune, append-then-sort.
// (unchanged from validated R5; ~25us)
// ---------------------------------------------------------------------------
__device__ __forceinline__ void isort(ull* a, int n)
{
    for (int i = 1; i < n; i++) {
        ull k = a[i];
        int m = i;
        while (m > 0 && a[m - 1] > k) { a[m] = a[m - 1]; m--; }
        a[m] = k;
    }
}

__global__ void __launch_bounds__(256) knn_kernel(const float* __restrict__ xyz,
                                                  const float* __restrict__ outxyz)
{
    __shared__ float4 sp[1024];                 // 16KB tile

    const int warp = threadIdx.x >> 5;
    const int lane = threadIdx.x & 31;
    const int gq = blockIdx.x * 8 + warp;       // global query id
    const int b = blockIdx.x >> 7;              // 128 blocks per batch

    const float qx = outxyz[gq * 3 + 0];
    const float qy = outxyz[gq * 3 + 1];
    const float qz = outxyz[gq * 3 + 2];
    const float q2 = fmaf(qx, qx, fmaf(qy, qy, qz * qz));

    ull arr[KNN];
    int cnt = 0;
    ull klim = ~0ull;
    bool sorted = false;
    const float r2 = 0.04f;

    const float* p = xyz + (size_t)b * NP * 3;

    for (int tile = 0; tile < 8; tile++) {
        const int base = tile << 10;
        for (int j = threadIdx.x; j < 1024; j += 256) {
            float x = p[(base + j) * 3 + 0];
            float y = p[(base + j) * 3 + 1];
            float z = p[(base + j) * 3 + 2];
            sp[j] = make_float4(x, y, z, fmaf(x, x, fmaf(y, y, z * z)));
        }
        __syncthreads();
#pragma unroll 4
        for (int jj = 0; jj < 32; jj++) {
            const int j = (jj << 5) + lane;
            float4 P = sp[j];
            float qp = fmaf(qx, P.x, fmaf(qy, P.y, qz * P.z));
            float d2 = fmaf(-2.0f, qp, q2 + P.w);
            if (d2 <= r2) {                                  // radius pre-prune
                unsigned du = __float_as_uint(d2);
                du ^= (unsigned)((int)du >> 31) | 0x80000000u;
                ull key = ((ull)du << 32) | (unsigned)(base + j);
                if (!sorted) {
                    arr[cnt++] = key;                        // cheap append
                    if (cnt == KNN) { isort(arr, KNN); klim = arr[KNN - 1]; sorted = true; }
                } else if (key < klim) {                     // rare overflow path
                    int m = KNN - 1;
                    while (m > 0 && arr[m - 1] > key) { arr[m] = arr[m - 1]; m--; }
                    arr[m] = key;
                    klim = arr[KNN - 1];
                }
            }
        }
        __syncthreads();
    }
    if (!sorted) isort(arr, cnt);

    // exact warp merge: 32 rounds of extract-min over per-lane sorted lists
    ull h = (cnt > 0) ? arr[0] : ~0ull;
    int ptr = 1;
    int nearidx = 0;
    int* dst = g_nbr + (size_t)gq * KNN;
    for (int k = 0; k < KNN; k++) {
        ull m = h;
#pragma unroll
        for (int o = 16; o > 0; o >>= 1) {
            ull x = __shfl_xor_sync(0xffffffffu, m, o);
            if (x < m) m = x;
        }
        if (k == 0) nearidx = (int)(m & 0xffffffffu);    // self always within radius
        int wi = (m == ~0ull) ? nearidx : (int)(m & 0xffffffffu);
        if (lane == k) dst[k] = wi;
        if (h == m && m != ~0ull)
            h = (ptr < cnt) ? arr[ptr++] : ~0ull;
    }
}

// ---------------------------------------------------------------------------
// Kernel 3 v7: v2 per-warp code, but 512 threads = 8 queries per block.
// Weights staged ONCE per 8 queries (halved staging traffic) and 16 warps/SM
// (vs v2's 8) with identical per-warp work. smem 138KB -> 1 block/SM.
// Accumulation order per output identical -> bit-exact.
// ---------------------------------------------------------------------------
template <int NU>
__device__ __forceinline__ void accum_row(ull* acc, const float* wrow, float xc)
{
    ull xv = bc2(xc);
    const ulonglong2* w = (const ulonglong2*)wrow;
#pragma unroll
    for (int jj = 0; jj < NU / 2; jj++) {
        ulonglong2 ww = w[jj];
        fma2(acc[2 * jj + 0], xv, ww.x);
        fma2(acc[2 * jj + 1], xv, ww.y);
    }
}

#define MLP_T 512
#define MLP_Q 8                            // queries per block
#define OW0 0
#define OB0 4288
#define OW1 4352
#define OB1 8448
#define OW2 8512
#define OB2 16704
#define OHBUF 16832                        // h exchange: 8 q * 32 n * 65
#define OPOOLV2 (OHBUF + MLP_Q * 32 * 65)  // 33472
#define SMEM_MLP_FLOATS (OPOOLV2 + MLP_Q * 128)
#define SMEM_MLP_BYTES (SMEM_MLP_FLOATS * 4)   // 137,984 B

__global__ void __launch_bounds__(MLP_T, 1) mlp_kernel(
    const float* __restrict__ xyz, const float* __restrict__ feat,
    const float* __restrict__ W0, const float* __restrict__ b0,
    const float* __restrict__ W1, const float* __restrict__ b1,
    const float* __restrict__ W2, const float* __restrict__ b2,
    float* __restrict__ out)
{
    extern __shared__ float sm[];
    // cooperative weight staging
    for (int i = threadIdx.x; i < OHBUF; i += MLP_T) {
        float v;
        if (i < OB0)        v = W0[i];
        else if (i < OW1)   v = b0[i - OB0];
        else if (i < OB1)   v = W1[i - OW1];
        else if (i < OW2)   v = b1[i - OB1];
        else if (i < OB2)   v = W2[i - OW2];
        else                v = b2[i - OB2];
        sm[i] = v;
    }

    const int warp = threadIdx.x >> 5;
    const int lane = threadIdx.x & 31;
    const int qlocal = warp >> 1;             // 0..7
    const int half = warp & 1;                // output-half owned by this warp
    const int q = blockIdx.x * MLP_Q + qlocal;
    const int b = q >> 10;

    const int nidx = g_nbr[q * KNN + lane];
    const float cx = out[q * 3 + 0];
    const float cy = out[q * 3 + 1];
    const float cz = out[q * 3 + 2];
    const float* pp = xyz + ((size_t)b * NP + nidx) * 3;
    const float x0 = pp[0] - cx;
    const float x1 = pp[1] - cy;
    const float x2 = pp[2] - cz;
    const float4* pf = (const float4*)(feat + ((size_t)b * NP + nidx) * F1);

    float* hq = sm + OHBUF + qlocal * (32 * 65);   // [neighbor][65]
    const int hrow = lane * 65;
    __syncthreads();                                // weights staged

    // ---- layer 1: 67 -> 64, this warp computes outs [half*32, half*32+32) ----
    ull a1[16];
    {
        const ull* bb = (const ull*)(sm + OB0) + half * 16;
#pragma unroll
        for (int j = 0; j < 16; j++) a1[j] = bb[j];
    }
    const int w0off = OW0 + half * 32;
    accum_row<16>(a1, sm + w0off + 0 * 64, x0);
    accum_row<16>(a1, sm + w0off + 1 * 64, x1);
    accum_row<16>(a1, sm + w0off + 2 * 64, x2);
#pragma unroll
    for (int g = 0; g < 16; g++) {
        float4 f = pf[g];
        accum_row<16>(a1, sm + w0off + (3 + 4 * g + 0) * 64, f.x);
        accum_row<16>(a1, sm + w0off + (3 + 4 * g + 1) * 64, f.y);
        accum_row<16>(a1, sm + w0off + (3 + 4 * g + 2) * 64, f.z);
        accum_row<16>(a1, sm + w0off + (3 + 4 * g + 3) * 64, f.w);
    }
#pragma unroll
    for (int j = 0; j < 16; j++) {
        float2 v = unpk(a1[j]);
        hq[hrow + half * 32 + 2 * j + 0] = lrelu(v.x);
        hq[hrow + half * 32 + 2 * j + 1] = lrelu(v.y);
    }
    __syncthreads();                                // h1 complete

    // ---- layer 2: 64 -> 64 (outs [half*32, half*32+32)) ----
    ull a2[16];
    {
        const ull* bb = (const ull*)(sm + OB1) + half * 16;
#pragma unroll
        for (int j = 0; j < 16; j++) a2[j] = bb[j];
    }
    const int w1off = OW1 + half * 32;
#pragma unroll 8
    for (int c = 0; c < 64; c++)
        accum_row<16>(a2, sm + w1off + c * 64, hq[hrow + c]);
    __syncthreads();                                // all h1 reads done
#pragma unroll
    for (int j = 0; j < 16; j++) {
        float2 v = unpk(a2[j]);
        hq[hrow + half * 32 + 2 * j + 0] = lrelu(v.x);
        hq[hrow + half * 32 + 2 * j + 1] = lrelu(v.y);
    }
    __syncthreads();                                // h2 complete

    // ---- layer 3: 64 -> 128 (outs [half*64, half*64+64), 2 chunks of 32) ----
    float* pool = sm + OPOOLV2 + qlocal * 128 + half * 64;
#pragma unroll
    for (int ch = 0; ch < 2; ch++) {
        ull a3[16];
        {
            const ull* bb = (const ull*)(sm + OB2) + half * 32 + ch * 16;
#pragma unroll
            for (int j = 0; j < 16; j++) a3[j] = bb[j];
        }
        const int w2off = OW2 + half * 64 + ch * 32;
#pragma unroll 8
        for (int c = 0; c < 64; c++)
            accum_row<16>(a3, sm + w2off + c * 128, hq[hrow + c]);
#pragma unroll
        for (int j = 0; j < 16; j++) {
            float2 v = unpk(a3[j]);
            float v0 = lrelu(v.x);
            float v1 = lrelu(v.y);
#pragma unroll
            for (int o = 16; o > 0; o >>= 1) {
                v0 = fmaxf(v0, __shfl_down_sync(0xffffffffu, v0, o));
                v1 = fmaxf(v1, __shfl_down_sync(0xffffffffu, v1, o));
            }
            if (lane == 0) {
                pool[ch * 32 + 2 * j + 0] = v0;
                pool[ch * 32 + 2 * j + 1] = v1;
            }
        }
    }
    __syncwarp();
    if (lane < 16) {
        float4* dst = (float4*)(out + BB * NQ * 3 + (size_t)q * 128 + half * 64);
        dst[lane] = ((const float4*)pool)[lane];
    }
}

// ---------------------------------------------------------------------------
extern "C" void kernel_launch(void* const* d_in, const int* in_sizes, int n_in,
                              void* d_out, int out_size)
{
    const float* xyz  = (const float*)d_in[0];
    const float* feat = (const float*)d_in[1];
    const float* W0   = (const float*)d_in[2];
    const float* b0   = (const float*)d_in[3];
    const float* W1   = (const float*)d_in[4];
    const float* b1   = (const float*)d_in[5];
    const float* W2   = (const float*)d_in[6];
    const float* b2   = (const float*)d_in[7];
    float* out = (float*)d_out;

    cudaFuncSetAttribute(fps_kernel, cudaFuncAttributeMaxDynamicSharedMemorySize,
                         3 * NP * 4);
    cudaFuncSetAttribute(mlp_kernel, cudaFuncAttributeMaxDynamicSharedMemorySize,
                         SMEM_MLP_BYTES);

    fps_kernel<<<BB, FPS_T, 3 * NP * 4>>>(xyz, out);
    knn_kernel<<<(BB * NQ) / 8, 256>>>(xyz, out);
    mlp_kernel<<<(BB * NQ) / MLP_Q, MLP_T, SMEM_MLP_BYTES>>>(xyz, feat, W0, b0,
                                                             W1, b1, W2, b2, out);
}

// round 15
// speedup vs baseline: 1.0976x; 1.0976x over previous
#include <cuda_runtime.h>
#include <cuda_bf16.h>

typedef unsigned long long ull;

#define BB 8
#define NP 8192
#define NQ 1024
#define KNN 32
#define F1 64

#define FPS_T 256
#define FPS_PAIRS 16               // 32 points per thread

// scratch: neighbor indices (radius-resolved), B*N2*K
__device__ int g_nbr[BB * NQ * KNN];

// ---------------- packed f32x2 helpers ----------------
union F2 { ull u; float2 f; };

__device__ __forceinline__ ull add2(ull a, ull b)
{
    ull r; asm("add.rn.f32x2 %0, %1, %2;" : "=l"(r) : "l"(a), "l"(b)); return r;
}
__device__ __forceinline__ ull mul2(ull a, ull b)
{
    ull r; asm("mul.rn.f32x2 %0, %1, %2;" : "=l"(r) : "l"(a), "l"(b)); return r;
}
__device__ __forceinline__ void fma2(ull& d, ull a, ull b)
{
    asm("fma.rn.f32x2 %0, %1, %2, %0;" : "+l"(d) : "l"(a), "l"(b));
}
__device__ __forceinline__ ull bc2(float x)
{
    ull r; asm("mov.b64 %0, {%1, %1};" : "=l"(r) : "f"(x)); return r;
}
__device__ __forceinline__ float2 unpk(ull r)
{
    float2 v; asm("mov.b64 {%0, %1}, %2;" : "=f"(v.x), "=f"(v.y) : "l"(r)); return v;
}
__device__ __forceinline__ float lrelu(float x) { return fmaxf(x, 0.2f * x); }

// ---------------------------------------------------------------------------
// Kernel 1: FPS (R12 structure, + exact tree-max over pair maxima).
// 1 block/batch, 256 threads, 32 pts/thread, single barrier/step,
// REDUX argmax with exact lowest-global-index tie semantics.
// ---------------------------------------------------------------------------
__global__ void __launch_bounds__(FPS_T, 1) fps_kernel(const float* __restrict__ xyz,
                                                       float* __restrict__ out)
{
    extern __shared__ float s[];            // sx/sy/sz: 3*8192 floats = 96KB
    float* sx = s;
    float* sy = s + NP;
    float* sz = s + 2 * NP;
    __shared__ unsigned swh[2][32];
    __shared__ int      swl[2][32];

    const int b = blockIdx.x;
    const int t = threadIdx.x;
    const int lane = t & 31;
    const int wid = t >> 5;                 // 0..7
    const float* p = xyz + (size_t)b * NP * 3;

    ull px[FPS_PAIRS], py[FPS_PAIRS], pz[FPS_PAIRS];
    float md[2 * FPS_PAIRS];
    float pm[FPS_PAIRS];
#pragma unroll
    for (int i = 0; i < FPS_PAIRS; i++) {
        int i0 = t + (2 * i) * FPS_T;
        int i1 = t + (2 * i + 1) * FPS_T;
        F2 X, Y, Z;
        X.f.x = p[i0 * 3 + 0]; Y.f.x = p[i0 * 3 + 1]; Z.f.x = p[i0 * 3 + 2];
        X.f.y = p[i1 * 3 + 0]; Y.f.y = p[i1 * 3 + 1]; Z.f.y = p[i1 * 3 + 2];
        px[i] = X.u; py[i] = Y.u; pz[i] = Z.u;
        sx[i0] = X.f.x; sy[i0] = Y.f.x; sz[i0] = Z.f.x;
        sx[i1] = X.f.y; sy[i1] = Y.f.y; sz[i1] = Z.f.y;
        md[2 * i] = 3.402823466e38f;
        md[2 * i + 1] = 3.402823466e38f;
    }
    if (wid == 0 && lane >= 8) {            // pad unused stage-2 slots
        swh[0][lane] = 0u; swh[1][lane] = 0u;
        swl[0][lane] = 0x7fffffff; swl[1][lane] = 0x7fffffff;
    }
    if (t == 0) {
        float* o = out + (size_t)b * NQ * 3;
        o[0] = p[0]; o[1] = p[1]; o[2] = p[2];
    }
    __syncthreads();

    float wx = p[0], wy = p[1], wz = p[2];  // current center (every thread)
    unsigned par = 0;
    for (int si = 1; si < NQ; si++) {
        const ull ncx = bc2(-wx), ncy = bc2(-wy), ncz = bc2(-wz);
#pragma unroll
        for (int i = 0; i < FPS_PAIRS; i++) {
            ull dx = add2(px[i], ncx);
            ull dy = add2(py[i], ncy);
            ull dz = add2(pz[i], ncz);
            ull d = mul2(dx, dx);
            fma2(d, dy, dy);
            fma2(d, dz, dz);
            float2 D = unpk(d);
            float m0 = fminf(md[2 * i], D.x);
            float m1 = fminf(md[2 * i + 1], D.y);
            md[2 * i] = m0;
            md[2 * i + 1] = m1;
            pm[i] = fmaxf(m0, m1);
        }
        // exact tree max over pm (fmax on finite values: order-independent)
        float t8[8];
#pragma unroll
        for (int i = 0; i < 8; i++) t8[i] = fmaxf(pm[i], pm[i + 8]);
#pragma unroll
        for (int st = 4; st > 0; st >>= 1)
#pragma unroll
            for (int i = 0; i < 4; i++)
                if (i < st) t8[i] = fmaxf(t8[i], t8[i + st]);
        const float tv = t8[0];
        // warp argmax via redux (all md >= 0 -> uint order == float order)
        const unsigned hi = __reduce_max_sync(0xffffffffu, __float_as_uint(tv));
        int cand = 0x7fffffff;
#pragma unroll
        for (int i = FPS_PAIRS - 1; i >= 0; i--) {
            if (__float_as_uint(pm[i]) == hi) {
                int slot = (__float_as_uint(md[2 * i]) == hi) ? (2 * i) : (2 * i + 1);
                cand = t + (slot << 8);     // global idx = t + slot*256
            }
        }
        const unsigned lo = __reduce_min_sync(0xffffffffu, (unsigned)cand);
        if (lane == 0) { swh[par][wid] = hi; swl[par][wid] = (int)lo; }
        __syncthreads();                                   // single barrier
        const unsigned h2 = swh[par][lane];
        const unsigned hh = __reduce_max_sync(0xffffffffu, h2);
        const unsigned c2 = (h2 == hh) ? (unsigned)swl[par][lane] : 0x7fffffffu;
        const int id = (int)__reduce_min_sync(0xffffffffu, c2);
        wx = sx[id]; wy = sy[id]; wz = sz[id];             // broadcast LDS
        if (t == 0) {
            float* o2 = out + (size_t)b * NQ * 3 + si * 3;
            o2[0] = wx; o2[1] = wy; o2[2] = wz;
        }
        par ^= 1;
    }
}

// ---------------------------------------------------------------------------
// Kernel 2: warp-per-query 32-NN, radius pre-prune, append-then-sort.
// (unchanged from validated R5; ~25us)
// ---------------------------------------------------------------------------
__device__ __forceinline__ void isort(ull* a, int n)
{
    for (int i = 1; i < n; i++) {
        ull k = a[i];
        int m = i;
        while (m > 0 && a[m - 1] > k) { a[m] = a[m - 1]; m--; }
        a[m] = k;
    }
}

__global__ void __launch_bounds__(256) knn_kernel(const float* __restrict__ xyz,
                                                  const float* __restrict__ outxyz)
{
    __shared__ float4 sp[1024];                 // 16KB tile

    const int warp = threadIdx.x >> 5;
    const int lane = threadIdx.x & 31;
    const int gq = blockIdx.x * 8 + warp;       // global query id
    const int b = blockIdx.x >> 7;              // 128 blocks per batch

    const float qx = outxyz[gq * 3 + 0];
    const float qy = outxyz[gq * 3 + 1];
    const float qz = outxyz[gq * 3 + 2];
    const float q2 = fmaf(qx, qx, fmaf(qy, qy, qz * qz));

    ull arr[KNN];
    int cnt = 0;
    ull klim = ~0ull;
    bool sorted = false;
    const float r2 = 0.04f;

    const float* p = xyz + (size_t)b * NP * 3;

    for (int tile = 0; tile < 8; tile++) {
        const int base = tile << 10;
        for (int j = threadIdx.x; j < 1024; j += 256) {
            float x = p[(base + j) * 3 + 0];
            float y = p[(base + j) * 3 + 1];
            float z = p[(base + j) * 3 + 2];
            sp[j] = make_float4(x, y, z, fmaf(x, x, fmaf(y, y, z * z)));
        }
        __syncthreads();
#pragma unroll 4
        for (int jj = 0; jj < 32; jj++) {
            const int j = (jj << 5) + lane;
            float4 P = sp[j];
            float qp = fmaf(qx, P.x, fmaf(qy, P.y, qz * P.z));
            float d2 = fmaf(-2.0f, qp, q2 + P.w);
            if (d2 <= r2) {                                  // radius pre-prune
                unsigned du = __float_as_uint(d2);
                du ^= (unsigned)((int)du >> 31) | 0x80000000u;
                ull key = ((ull)du << 32) | (unsigned)(base + j);
                if (!sorted) {
                    arr[cnt++] = key;                        // cheap append
                    if (cnt == KNN) { isort(arr, KNN); klim = arr[KNN - 1]; sorted = true; }
                } else if (key < klim) {                     // rare overflow path
                    int m = KNN - 1;
                    while (m > 0 && arr[m - 1] > key) { arr[m] = arr[m - 1]; m--; }
                    arr[m] = key;
                    klim = arr[KNN - 1];
                }
            }
        }
        __syncthreads();
    }
    if (!sorted) isort(arr, cnt);

    // exact warp merge: 32 rounds of extract-min over per-lane sorted lists
    ull h = (cnt > 0) ? arr[0] : ~0ull;
    int ptr = 1;
    int nearidx = 0;
    int* dst = g_nbr + (size_t)gq * KNN;
    for (int k = 0; k < KNN; k++) {
        ull m = h;
#pragma unroll
        for (int o = 16; o > 0; o >>= 1) {
            ull x = __shfl_xor_sync(0xffffffffu, m, o);
            if (x < m) m = x;
        }
        if (k == 0) nearidx = (int)(m & 0xffffffffu);    // self always within radius
        int wi = (m == ~0ull) ? nearidx : (int)(m & 0xffffffffu);
        if (lane == k) dst[k] = wi;
        if (h == m && m != ~0ull)
            h = (ptr < cnt) ? arr[ptr++] : ~0ull;
    }
}

// ---------------------------------------------------------------------------
// Kernel 3 v8: warp = 2 queries x half-channels. Each weight LDS.128 feeds
// 32 FMA2 (two accumulator sets) -> weight-LDS traffic halved vs v2/v7.
// Layer 3 in 2 chunks of 32 channels to keep live accumulators at 64 regs.
// 512 threads = 16 queries/block; smem 204KB (weights 67K + act 130K + pool).
// Accumulation order per output identical -> bit-exact.
// ---------------------------------------------------------------------------
template <int NU>
__device__ __forceinline__ void accum_row2(ull* a, ull* b, const float* wrow,
                                           float xa, float xb)
{
    ull va = bc2(xa), vb = bc2(xb);
    const ulonglong2* w = (const ulonglong2*)wrow;
#pragma unroll
    for (int jj = 0; jj < NU / 2; jj++) {
        ulonglong2 ww = w[jj];
        fma2(a[2 * jj + 0], va, ww.x);
        fma2(a[2 * jj + 1], va, ww.y);
        fma2(b[2 * jj + 0], vb, ww.x);
        fma2(b[2 * jj + 1], vb, ww.y);
    }
}

#define MLP_T 512
#define MLP_Q 16                           // queries per block
#define OW0 0
#define OB0 4288
#define OW1 4352
#define OB1 8448
#define OW2 8512
#define OB2 16704
#define OHBUF 16832                        // act: 16 q * 32 n * 65
#define OPOOLV (OHBUF + MLP_Q * 32 * 65)   // 50112
#define SMEM_MLP_FLOATS (OPOOLV + MLP_Q * 128)
#define SMEM_MLP_BYTES (SMEM_MLP_FLOATS * 4)   // 208,640 B

__global__ void __launch_bounds__(MLP_T, 1) mlp_kernel(
    const float* __restrict__ xyz, const float* __restrict__ feat,
    const float* __restrict__ W0, const float* __restrict__ b0,
    const float* __restrict__ W1, const float* __restrict__ b1,
    const float* __restrict__ W2, const float* __restrict__ b2,
    float* __restrict__ out)
{
    extern __shared__ float sm[];
    // cooperative weight staging
    for (int i = threadIdx.x; i < OHBUF; i += MLP_T) {
        float v;
        if (i < OB0)        v = W0[i];
        else if (i < OW1)   v = b0[i - OB0];
        else if (i < OB1)   v = W1[i - OW1];
        else if (i < OW2)   v = b1[i - OB1];
        else if (i < OB2)   v = W2[i - OW2];
        else                v = b2[i - OB2];
        sm[i] = v;
    }

    const int warp = threadIdx.x >> 5;
    const int lane = threadIdx.x & 31;
    const int pair = warp >> 1;               // 0..7 -> queries 2p, 2p+1
    const int half = warp & 1;                // output-half owned by this warp
    const int q0 = blockIdx.x * MLP_Q + pair * 2;
    const int q1 = q0 + 1;
    const int bb = q0 >> 10;                  // same batch for q0,q1 (16|1024)

    const int ni0 = g_nbr[q0 * KNN + lane];
    const int ni1 = g_nbr[q1 * KNN + lane];
    const float* pp0 = xyz + ((size_t)bb * NP + ni0) * 3;
    const float* pp1 = xyz + ((size_t)bb * NP + ni1) * 3;
    const float x00 = pp0[0] - out[q0 * 3 + 0];
    const float x01 = pp0[1] - out[q0 * 3 + 1];
    const float x02 = pp0[2] - out[q0 * 3 + 2];
    const float x10 = pp1[0] - out[q1 * 3 + 0];
    const float x11 = pp1[1] - out[q1 * 3 + 1];
    const float x12 = pp1[2] - out[q1 * 3 + 2];
    const float4* pf0 = (const float4*)(feat + ((size_t)bb * NP + ni0) * F1);
    const float4* pf1 = (const float4*)(feat + ((size_t)bb * NP + ni1) * F1);

    float* hq0 = sm + OHBUF + (pair * 2 + 0) * (32 * 65);  // [neighbor][65]
    float* hq1 = sm + OHBUF + (pair * 2 + 1) * (32 * 65);
    const int hrow = lane * 65;
    __syncthreads();                                // weights staged

    // ---- layer 1: 67 -> 64, outs [half*32, half*32+32) for q0 and q1 ----
    ull A[16], B[16];
    {
        const ull* bp = (const ull*)(sm + OB0) + half * 16;
#pragma unroll
        for (int j = 0; j < 16; j++) { A[j] = bp[j]; B[j] = bp[j]; }
    }
    const int w0off = OW0 + half * 32;
    accum_row2<16>(A, B, sm + w0off + 0 * 64, x00, x10);
    accum_row2<16>(A, B, sm + w0off + 1 * 64, x01, x11);
    accum_row2<16>(A, B, sm + w0off + 2 * 64, x02, x12);
#pragma unroll
    for (int g = 0; g < 16; g++) {
        float4 f0 = pf0[g];
        float4 f1 = pf1[g];
        accum_row2<16>(A, B, sm + w0off + (3 + 4 * g + 0) * 64, f0.x, f1.x);
        accum_row2<16>(A, B, sm + w0off + (3 + 4 * g + 1) * 64, f0.y, f1.y);
        accum_row2<16>(A, B, sm + w0off + (3 + 4 * g + 2) * 64, f0.z, f1.z);
        accum_row2<16>(A, B, sm + w0off + (3 + 4 * g + 3) * 64, f0.w, f1.w);
    }
#pragma unroll
    for (int j = 0; j < 16; j++) {
        float2 va = unpk(A[j]);
        float2 vb = unpk(B[j]);
        hq0[hrow + half * 32 + 2 * j + 0] = lrelu(va.x);
        hq0[hrow + half * 32 + 2 * j + 1] = lrelu(va.y);
        hq1[hrow + half * 32 + 2 * j + 0] = lrelu(vb.x);
        hq1[hrow + half * 32 + 2 * j + 1] = lrelu(vb.y);
    }
    __syncthreads();                                // h1 complete

    // ---- layer 2: 64 -> 64 (outs [half*32, +32)) ----
    {
        const ull* bp = (const ull*)(sm + OB1) + half * 16;
#pragma unroll
        for (int j = 0; j < 16; j++) { A[j] = bp[j]; B[j] = bp[j]; }
    }
    const int w1off = OW1 + half * 32;
#pragma unroll 8
    for (int c = 0; c < 64; c++)
        accum_row2<16>(A, B, sm + w1off + c * 64, hq0[hrow + c], hq1[hrow + c]);
    __syncthreads();                                // all h1 reads done
#pragma unroll
    for (int j = 0; j < 16; j++) {
        float2 va = unpk(A[j]);
        float2 vb = unpk(B[j]);
        hq0[hrow + half * 32 + 2 * j + 0] = lrelu(va.x);
        hq0[hrow + half * 32 + 2 * j + 1] = lrelu(va.y);
        hq1[hrow + half * 32 + 2 * j + 0] = lrelu(vb.x);
        hq1[hrow + half * 32 + 2 * j + 1] = lrelu(vb.y);
    }
    __syncthreads();                                // h2 complete

    // ---- layer 3: 64 -> 128 (outs [half*64, +64), 2 chunks of 32) ----
    float* pool0 = sm + OPOOLV + (pair * 2 + 0) * 128 + half * 64;
    float* pool1 = sm + OPOOLV + (pair * 2 + 1) * 128 + half * 64;
#pragma unroll
    for (int ch = 0; ch < 2; ch++) {
        {
            const ull* bp = (const ull*)(sm + OB2) + half * 32 + ch * 16;
#pragma unroll
            for (int j = 0; j < 16; j++) { A[j] = bp[j]; B[j] = bp[j]; }
        }
        const int w2off = OW2 + half * 64 + ch * 32;
#pragma unroll 8
        for (int c = 0; c < 64; c++)
            accum_row2<16>(A, B, sm + w2off + c * 128, hq0[hrow + c], hq1[hrow + c]);
#pragma unroll
        for (int j = 0; j < 16; j++) {
            float2 va = unpk(A[j]);
            float2 vb = unpk(B[j]);
            float a0 = lrelu(va.x), a1 = lrelu(va.y);
            float b0v = lrelu(vb.x), b1v = lrelu(vb.y);
#pragma unroll
            for (int o = 16; o > 0; o >>= 1) {
                a0 = fmaxf(a0, __shfl_down_sync(0xffffffffu, a0, o));
                a1 = fmaxf(a1, __shfl_down_sync(0xffffffffu, a1, o));
                b0v = fmaxf(b0v, __shfl_down_sync(0xffffffffu, b0v, o));
                b1v = fmaxf(b1v, __shfl_down_sync(0xffffffffu, b1v, o));
            }
            if (lane == 0) {
                pool0[ch * 32 + 2 * j + 0] = a0;
                pool0[ch * 32 + 2 * j + 1] = a1;
                pool1[ch * 32 + 2 * j + 0] = b0v;
                pool1[ch * 32 + 2 * j + 1] = b1v;
            }
        }
    }
    __syncwarp();
    {
        const int sel = lane >> 4;                 // 0 -> q0, 1 -> q1
        const int li = lane & 15;
        const int qq = sel ? q1 : q0;
        const float* pp = sel ? pool1 : pool0;
        float4* dst = (float4*)(out + BB * NQ * 3 + (size_t)qq * 128 + half * 64);
        dst[li] = ((const float4*)pp)[li];
    }
}

// ---------------------------------------------------------------------------
extern "C" void kernel_launch(void* const* d_in, const int* in_sizes, int n_in,
                              void* d_out, int out_size)
{
    const float* xyz  = (const float*)d_in[0];
    const float* feat = (const float*)d_in[1];
    const float* W0   = (const float*)d_in[2];
    const float* b0   = (const float*)d_in[3];
    const float* W1   = (const float*)d_in[4];
    const float* b1   = (const float*)d_in[5];
    const float* W2   = (const float*)d_in[6];
    const float* b2   = (const float*)d_in[7];
    float* out = (float*)d_out;

    cudaFuncSetAttribute(fps_kernel, cudaFuncAttributeMaxDynamicSharedMemorySize,
                         3 * NP * 4);
    cudaFuncSetAttribute(mlp_kernel, cudaFuncAttributeMaxDynamicSharedMemorySize,
                         SMEM_MLP_BYTES);

    fps_kernel<<<BB, FPS_T, 3 * NP * 4>>>(xyz, out);
    knn_kernel<<<(BB * NQ) / 8, 256>>>(xyz, out);
    mlp_kernel<<<(BB * NQ) / MLP_Q, MLP_T, SMEM_MLP_BYTES>>>(xyz, feat, W0, b0,
                                                             W1, b1, W2, b2, out);
}

// round 16
// speedup vs baseline: 1.1146x; 1.0156x over previous
#include <cuda_runtime.h>
#include <cuda_bf16.h>

typedef unsigned long long ull;

#define BB 8
#define NP 8192
#define NQ 1024
#define KNN 32
#define F1 64

#define FPS_T 256
#define FPS_PAIRS 16               // 32 points per thread

// scratch: neighbor indices (radius-resolved), B*N2*K
__device__ int g_nbr[BB * NQ * KNN];

// ---------------- packed f32x2 helpers ----------------
union F2 { ull u; float2 f; };

__device__ __forceinline__ ull add2(ull a, ull b)
{
    ull r; asm("add.rn.f32x2 %0, %1, %2;" : "=l"(r) : "l"(a), "l"(b)); return r;
}
__device__ __forceinline__ ull mul2(ull a, ull b)
{
    ull r; asm("mul.rn.f32x2 %0, %1, %2;" : "=l"(r) : "l"(a), "l"(b)); return r;
}
__device__ __forceinline__ void fma2(ull& d, ull a, ull b)
{
    asm("fma.rn.f32x2 %0, %1, %2, %0;" : "+l"(d) : "l"(a), "l"(b));
}
__device__ __forceinline__ ull bc2(float x)
{
    ull r; asm("mov.b64 %0, {%1, %1};" : "=l"(r) : "f"(x)); return r;
}
__device__ __forceinline__ float2 unpk(ull r)
{
    float2 v; asm("mov.b64 {%0, %1}, %2;" : "=f"(v.x), "=f"(v.y) : "l"(r)); return v;
}
__device__ __forceinline__ float lrelu(float x) { return fmaxf(x, 0.2f * x); }

#define PAIR_BAR(pid) \
    asm volatile("bar.sync %0, 64;" :: "r"(1 + (pid)) : "memory")

// ---------------------------------------------------------------------------
// Kernel 1: FPS (R15, measured 494-498us). 1 block/batch, 256 threads,
// 32 pts/thread, single barrier/step, REDUX argmax, exact lowest-index ties.
// ---------------------------------------------------------------------------
__global__ void __launch_bounds__(FPS_T, 1) fps_kernel(const float* __restrict__ xyz,
                                                       float* __restrict__ out)
{
    extern __shared__ float s[];            // sx/sy/sz: 3*8192 floats = 96KB
    float* sx = s;
    float* sy = s + NP;
    float* sz = s + 2 * NP;
    __shared__ unsigned swh[2][32];
    __shared__ int      swl[2][32];

    const int b = blockIdx.x;
    const int t = threadIdx.x;
    const int lane = t & 31;
    const int wid = t >> 5;                 // 0..7
    const float* p = xyz + (size_t)b * NP * 3;

    ull px[FPS_PAIRS], py[FPS_PAIRS], pz[FPS_PAIRS];
    float md[2 * FPS_PAIRS];
    float pm[FPS_PAIRS];
#pragma unroll
    for (int i = 0; i < FPS_PAIRS; i++) {
        int i0 = t + (2 * i) * FPS_T;
        int i1 = t + (2 * i + 1) * FPS_T;
        F2 X, Y, Z;
        X.f.x = p[i0 * 3 + 0]; Y.f.x = p[i0 * 3 + 1]; Z.f.x = p[i0 * 3 + 2];
        X.f.y = p[i1 * 3 + 0]; Y.f.y = p[i1 * 3 + 1]; Z.f.y = p[i1 * 3 + 2];
        px[i] = X.u; py[i] = Y.u; pz[i] = Z.u;
        sx[i0] = X.f.x; sy[i0] = Y.f.x; sz[i0] = Z.f.x;
        sx[i1] = X.f.y; sy[i1] = Y.f.y; sz[i1] = Z.f.y;
        md[2 * i] = 3.402823466e38f;
        md[2 * i + 1] = 3.402823466e38f;
    }
    if (wid == 0 && lane >= 8) {            // pad unused stage-2 slots
        swh[0][lane] = 0u; swh[1][lane] = 0u;
        swl[0][lane] = 0x7fffffff; swl[1][lane] = 0x7fffffff;
    }
    if (t == 0) {
        float* o = out + (size_t)b * NQ * 3;
        o[0] = p[0]; o[1] = p[1]; o[2] = p[2];
    }
    __syncthreads();

    float wx = p[0], wy = p[1], wz = p[2];  // current center (every thread)
    unsigned par = 0;
    for (int si = 1; si < NQ; si++) {
        const ull ncx = bc2(-wx), ncy = bc2(-wy), ncz = bc2(-wz);
#pragma unroll
        for (int i = 0; i < FPS_PAIRS; i++) {
            ull dx = add2(px[i], ncx);
            ull dy = add2(py[i], ncy);
            ull dz = add2(pz[i], ncz);
            ull d = mul2(dx, dx);
            fma2(d, dy, dy);
            fma2(d, dz, dz);
            float2 D = unpk(d);
            float m0 = fminf(md[2 * i], D.x);
            float m1 = fminf(md[2 * i + 1], D.y);
            md[2 * i] = m0;
            md[2 * i + 1] = m1;
            pm[i] = fmaxf(m0, m1);
        }
        // exact tree max over pm (fmax on finite values: order-independent)
        float t8[8];
#pragma unroll
        for (int i = 0; i < 8; i++) t8[i] = fmaxf(pm[i], pm[i + 8]);
#pragma unroll
        for (int st = 4; st > 0; st >>= 1)
#pragma unroll
            for (int i = 0; i < 4; i++)
                if (i < st) t8[i] = fmaxf(t8[i], t8[i + st]);
        const float tv = t8[0];
        // warp argmax via redux (all md >= 0 -> uint order == float order)
        const unsigned hi = __reduce_max_sync(0xffffffffu, __float_as_uint(tv));
        int cand = 0x7fffffff;
#pragma unroll
        for (int i = FPS_PAIRS - 1; i >= 0; i--) {
            if (__float_as_uint(pm[i]) == hi) {
                int slot = (__float_as_uint(md[2 * i]) == hi) ? (2 * i) : (2 * i + 1);
                cand = t + (slot << 8);     // global idx = t + slot*256
            }
        }
        const unsigned lo = __reduce_min_sync(0xffffffffu, (unsigned)cand);
        if (lane == 0) { swh[par][wid] = hi; swl[par][wid] = (int)lo; }
        __syncthreads();                                   // single barrier
        const unsigned h2 = swh[par][lane];
        const unsigned hh = __reduce_max_sync(0xffffffffu, h2);
        const unsigned c2 = (h2 == hh) ? (unsigned)swl[par][lane] : 0x7fffffffu;
        const int id = (int)__reduce_min_sync(0xffffffffu, c2);
        wx = sx[id]; wy = sy[id]; wz = sz[id];             // broadcast LDS
        if (t == 0) {
            float* o2 = out + (size_t)b * NQ * 3 + si * 3;
            o2[0] = wx; o2[1] = wy; o2[2] = wz;
        }
        par ^= 1;
    }
}

// ---------------------------------------------------------------------------
// Kernel 2: warp-per-query 32-NN, radius pre-prune, append-then-sort.
// (unchanged from validated R5; ~25us)
// ---------------------------------------------------------------------------
__device__ __forceinline__ void isort(ull* a, int n)
{
    for (int i = 1; i < n; i++) {
        ull k = a[i];
        int m = i;
        while (m > 0 && a[m - 1] > k) { a[m] = a[m - 1]; m--; }
        a[m] = k;
    }
}

__global__ void __launch_bounds__(256) knn_kernel(const float* __restrict__ xyz,
                                                  const float* __restrict__ outxyz)
{
    __shared__ float4 sp[1024];                 // 16KB tile

    const int warp = threadIdx.x >> 5;
    const int lane = threadIdx.x & 31;
    const int gq = blockIdx.x * 8 + warp;       // global query id
    const int b = blockIdx.x >> 7;              // 128 blocks per batch

    const float qx = outxyz[gq * 3 + 0];
    const float qy = outxyz[gq * 3 + 1];
    const float qz = outxyz[gq * 3 + 2];
    const float q2 = fmaf(qx, qx, fmaf(qy, qy, qz * qz));

    ull arr[KNN];
    int cnt = 0;
    ull klim = ~0ull;
    bool sorted = false;
    const float r2 = 0.04f;

    const float* p = xyz + (size_t)b * NP * 3;

    for (int tile = 0; tile < 8; tile++) {
        const int base = tile << 10;
        for (int j = threadIdx.x; j < 1024; j += 256) {
            float x = p[(base + j) * 3 + 0];
            float y = p[(base + j) * 3 + 1];
            float z = p[(base + j) * 3 + 2];
            sp[j] = make_float4(x, y, z, fmaf(x, x, fmaf(y, y, z * z)));
        }
        __syncthreads();
#pragma unroll 4
        for (int jj = 0; jj < 32; jj++) {
            const int j = (jj << 5) + lane;
            float4 P = sp[j];
            float qp = fmaf(qx, P.x, fmaf(qy, P.y, qz * P.z));
            float d2 = fmaf(-2.0f, qp, q2 + P.w);
            if (d2 <= r2) {                                  // radius pre-prune
                unsigned du = __float_as_uint(d2);
                du ^= (unsigned)((int)du >> 31) | 0x80000000u;
                ull key = ((ull)du << 32) | (unsigned)(base + j);
                if (!sorted) {
                    arr[cnt++] = key;                        // cheap append
                    if (cnt == KNN) { isort(arr, KNN); klim = arr[KNN - 1]; sorted = true; }
                } else if (key < klim) {                     // rare overflow path
                    int m = KNN - 1;
                    while (m > 0 && arr[m - 1] > key) { arr[m] = arr[m - 1]; m--; }
                    arr[m] = key;
                    klim = arr[KNN - 1];
                }
            }
        }
        __syncthreads();
    }
    if (!sorted) isort(arr, cnt);

    // exact warp merge: 32 rounds of extract-min over per-lane sorted lists
    ull h = (cnt > 0) ? arr[0] : ~0ull;
    int ptr = 1;
    int nearidx = 0;
    int* dst = g_nbr + (size_t)gq * KNN;
    for (int k = 0; k < KNN; k++) {
        ull m = h;
#pragma unroll
        for (int o = 16; o > 0; o >>= 1) {
            ull x = __shfl_xor_sync(0xffffffffu, m, o);
            if (x < m) m = x;
        }
        if (k == 0) nearidx = (int)(m & 0xffffffffu);    // self always within radius
        int wi = (m == ~0ull) ? nearidx : (int)(m & 0xffffffffu);
        if (lane == k) dst[k] = wi;
        if (h == m && m != ~0ull)
            h = (ptr < cnt) ? arr[ptr++] : ~0ull;
    }
}

// ---------------------------------------------------------------------------
// Kernel 3 v9: v8 (warp = 2 queries x half-channels, dual accumulators) with
// PER-PAIR named barriers (bar.sync 1+pair, 64) instead of block-wide
// __syncthreads at layer boundaries — pairs flow independently, skew no
// longer serializes all 16 warps. Deeper unroll (16) to front-batch LDS.
// Accumulation order per output identical -> bit-exact.
// ---------------------------------------------------------------------------
template <int NU>
__device__ __forceinline__ void accum_row2(ull* a, ull* b, const float* wrow,
                                           float xa, float xb)
{
    ull va = bc2(xa), vb = bc2(xb);
    const ulonglong2* w = (const ulonglong2*)wrow;
#pragma unroll
    for (int jj = 0; jj < NU / 2; jj++) {
        ulonglong2 ww = w[jj];
        fma2(a[2 * jj + 0], va, ww.x);
        fma2(a[2 * jj + 1], va, ww.y);
        fma2(b[2 * jj + 0], vb, ww.x);
        fma2(b[2 * jj + 1], vb, ww.y);
    }
}

#define MLP_T 512
#define MLP_Q 16                           // queries per block
#define OW0 0
#define OB0 4288
#define OW1 4352
#define OB1 8448
#define OW2 8512
#define OB2 16704
#define OHBUF 16832                        // act: 16 q * 32 n * 65
#define OPOOLV (OHBUF + MLP_Q * 32 * 65)   // 50112
#define SMEM_MLP_FLOATS (OPOOLV + MLP_Q * 128)
#define SMEM_MLP_BYTES (SMEM_MLP_FLOATS * 4)   // 208,640 B

__global__ void __launch_bounds__(MLP_T, 1) mlp_kernel(
    const float* __restrict__ xyz, const float* __restrict__ feat,
    const float* __restrict__ W0, const float* __restrict__ b0,
    const float* __restrict__ W1, const float* __restrict__ b1,
    const float* __restrict__ W2, const float* __restrict__ b2,
    float* __restrict__ out)
{
    extern __shared__ float sm[];
    // cooperative weight staging
    for (int i = threadIdx.x; i < OHBUF; i += MLP_T) {
        float v;
        if (i < OB0)        v = W0[i];
        else if (i < OW1)   v = b0[i - OB0];
        else if (i < OB1)   v = W1[i - OW1];
        else if (i < OW2)   v = b1[i - OB1];
        else if (i < OB2)   v = W2[i - OW2];
        else                v = b2[i - OB2];
        sm[i] = v;
    }

    const int warp = threadIdx.x >> 5;
    const int lane = threadIdx.x & 31;
    const int pair = warp >> 1;               // 0..7 -> queries 2p, 2p+1
    const int half = warp & 1;                // output-half owned by this warp
    const int q0 = blockIdx.x * MLP_Q + pair * 2;
    const int q1 = q0 + 1;
    const int bb = q0 >> 10;                  // same batch for q0,q1 (16|1024)

    const int ni0 = g_nbr[q0 * KNN + lane];
    const int ni1 = g_nbr[q1 * KNN + lane];
    const float* pp0 = xyz + ((size_t)bb * NP + ni0) * 3;
    const float* pp1 = xyz + ((size_t)bb * NP + ni1) * 3;
    const float x00 = pp0[0] - out[q0 * 3 + 0];
    const float x01 = pp0[1] - out[q0 * 3 + 1];
    const float x02 = pp0[2] - out[q0 * 3 + 2];
    const float x10 = pp1[0] - out[q1 * 3 + 0];
    const float x11 = pp1[1] - out[q1 * 3 + 1];
    const float x12 = pp1[2] - out[q1 * 3 + 2];
    const float4* pf0 = (const float4*)(feat + ((size_t)bb * NP + ni0) * F1);
    const float4* pf1 = (const float4*)(feat + ((size_t)bb * NP + ni1) * F1);

    float* hq0 = sm + OHBUF + (pair * 2 + 0) * (32 * 65);  // [neighbor][65]
    float* hq1 = sm + OHBUF + (pair * 2 + 1) * (32 * 65);
    const int hrow = lane * 65;
    __syncthreads();                                // weights staged (block-wide)

    // ---- layer 1: 67 -> 64, outs [half*32, half*32+32) for q0 and q1 ----
    ull A[16], B[16];
    {
        const ull* bp = (const ull*)(sm + OB0) + half * 16;
#pragma unroll
        for (int j = 0; j < 16; j++) { A[j] = bp[j]; B[j] = bp[j]; }
    }
    const int w0off = OW0 + half * 32;
    accum_row2<16>(A, B, sm + w0off + 0 * 64, x00, x10);
    accum_row2<16>(A, B, sm + w0off + 1 * 64, x01, x11);
    accum_row2<16>(A, B, sm + w0off + 2 * 64, x02, x12);
#pragma unroll
    for (int g = 0; g < 16; g++) {
        float4 f0 = pf0[g];
        float4 f1 = pf1[g];
        accum_row2<16>(A, B, sm + w0off + (3 + 4 * g + 0) * 64, f0.x, f1.x);
        accum_row2<16>(A, B, sm + w0off + (3 + 4 * g + 1) * 64, f0.y, f1.y);
        accum_row2<16>(A, B, sm + w0off + (3 + 4 * g + 2) * 64, f0.z, f1.z);
        accum_row2<16>(A, B, sm + w0off + (3 + 4 * g + 3) * 64, f0.w, f1.w);
    }
#pragma unroll
    for (int j = 0; j < 16; j++) {
        float2 va = unpk(A[j]);
        float2 vb = unpk(B[j]);
        hq0[hrow + half * 32 + 2 * j + 0] = lrelu(va.x);
        hq0[hrow + half * 32 + 2 * j + 1] = lrelu(va.y);
        hq1[hrow + half * 32 + 2 * j + 0] = lrelu(vb.x);
        hq1[hrow + half * 32 + 2 * j + 1] = lrelu(vb.y);
    }
    PAIR_BAR(pair);                                 // h1 complete (pair-local)

    // ---- layer 2: 64 -> 64 (outs [half*32, +32)) ----
    {
        const ull* bp = (const ull*)(sm + OB1) + half * 16;
#pragma unroll
        for (int j = 0; j < 16; j++) { A[j] = bp[j]; B[j] = bp[j]; }
    }
    const int w1off = OW1 + half * 32;
#pragma unroll 16
    for (int c = 0; c < 64; c++)
        accum_row2<16>(A, B, sm + w1off + c * 64, hq0[hrow + c], hq1[hrow + c]);
    PAIR_BAR(pair);                                 // all h1 reads done
#pragma unroll
    for (int j = 0; j < 16; j++) {
        float2 va = unpk(A[j]);
        float2 vb = unpk(B[j]);
        hq0[hrow + half * 32 + 2 * j + 0] = lrelu(va.x);
        hq0[hrow + half * 32 + 2 * j + 1] = lrelu(va.y);
        hq1[hrow + half * 32 + 2 * j + 0] = lrelu(vb.x);
        hq1[hrow + half * 32 + 2 * j + 1] = lrelu(vb.y);
    }
    PAIR_BAR(pair);                                 // h2 complete (pair-local)

    // ---- layer 3: 64 -> 128 (outs [half*64, +64), 2 chunks of 32) ----
    float* pool0 = sm + OPOOLV + (pair * 2 + 0) * 128 + half * 64;
    float* pool1 = sm + OPOOLV + (pair * 2 + 1) * 128 + half * 64;
#pragma unroll
    for (int ch = 0; ch < 2; ch++) {
        {
            const ull* bp = (const ull*)(sm + OB2) + half * 32 + ch * 16;
#pragma unroll
            for (int j = 0; j < 16; j++) { A[j] = bp[j]; B[j] = bp[j]; }
        }
        const int w2off = OW2 + half * 64 + ch * 32;
#pragma unroll 16
        for (int c = 0; c < 64; c++)
            accum_row2<16>(A, B, sm + w2off + c * 128, hq0[hrow + c], hq1[hrow + c]);
#pragma unroll
        for (int j = 0; j < 16; j++) {
            float2 va = unpk(A[j]);
            float2 vb = unpk(B[j]);
            float a0 = lrelu(va.x), a1 = lrelu(va.y);
            float b0v = lrelu(vb.x), b1v = lrelu(vb.y);
#pragma unroll
            for (int o = 16; o > 0; o >>= 1) {
                a0 = fmaxf(a0, __shfl_down_sync(0xffffffffu, a0, o));
                a1 = fmaxf(a1, __shfl_down_sync(0xffffffffu, a1, o));
                b0v = fmaxf(b0v, __shfl_down_sync(0xffffffffu, b0v, o));
                b1v = fmaxf(b1v, __shfl_down_sync(0xffffffffu, b1v, o));
            }
            if (lane == 0) {
                pool0[ch * 32 + 2 * j + 0] = a0;
                pool0[ch * 32 + 2 * j + 1] = a1;
                pool1[ch * 32 + 2 * j + 0] = b0v;
                pool1[ch * 32 + 2 * j + 1] = b1v;
            }
        }
    }
    __syncwarp();
    {
        const int sel = lane >> 4;                 // 0 -> q0, 1 -> q1
        const int li = lane & 15;
        const int qq = sel ? q1 : q0;
        const float* pp = sel ? pool1 : pool0;
        float4* dst = (float4*)(out + BB * NQ * 3 + (size_t)qq * 128 + half * 64);
        dst[li] = ((const float4*)pp)[li];
    }
}

// ---------------------------------------------------------------------------
extern "C" void kernel_launch(void* const* d_in, const int* in_sizes, int n_in,
                              void* d_out, int out_size)
{
    const float* xyz  = (const float*)d_in[0];
    const float* feat = (const float*)d_in[1];
    const float* W0   = (const float*)d_in[2];
    const float* b0   = (const float*)d_in[3];
    const float* W1   = (const float*)d_in[4];
    const float* b1   = (const float*)d_in[5];
    const float* W2   = (const float*)d_in[6];
    const float* b2   = (const float*)d_in[7];
    float* out = (float*)d_out;

    cudaFuncSetAttribute(fps_kernel, cudaFuncAttributeMaxDynamicSharedMemorySize,
                         3 * NP * 4);
    cudaFuncSetAttribute(mlp_kernel, cudaFuncAttributeMaxDynamicSharedMemorySize,
                         SMEM_MLP_BYTES);

    fps_kernel<<<BB, FPS_T, 3 * NP * 4>>>(xyz, out);
    knn_kernel<<<(BB * NQ) / 8, 256>>>(xyz, out);
    mlp_kernel<<<(BB * NQ) / MLP_Q, MLP_T, SMEM_MLP_BYTES>>>(xyz, feat, W0, b0,
                                                             W1, b1, W2, b2, out);
}